// round 3
// baseline (speedup 1.0000x reference)
#include <cuda_runtime.h>

#define D_IN   1024
#define D_OUT  1024
#define BATCH  32
#define E_TOT  3076              // D_OUT + 2*D_IN + 4
#define E_TAIL 2052              // E_TOT - D_OUT (rows needed in pass 1)

// Scratch (device globals; no allocation allowed)
__device__ float g_out [BATCH * E_TAIL];   // w·x for rows [D_OUT, E)
__device__ float g_kphi[BATCH * D_IN];     // softmax(k)
__device__ float g_diff[BATCH * D_IN];     // softmax(q) - softmax(k)
__device__ float g_sigb[BATCH * 4];        // sigmoid(b1..b4)

// ---------------------------------------------------------------------------
// Kernel 1: out[b, e] = dot(w[b, D_OUT+e, :], x[b, :]) for e in [0, E_TAIL)
// warp-per-row, 8 warps/block, streaming loads of w.
// ---------------------------------------------------------------------------
__global__ void __launch_bounds__(256) k1_gemv(const float* __restrict__ x,
                                               const float* __restrict__ w)
{
    __shared__ float xs[D_IN];
    const int b   = blockIdx.y;
    const int tid = threadIdx.x;

    const float4* x4 = (const float4*)(x + (size_t)b * D_IN);
    for (int i = tid; i < D_IN / 4; i += 256)
        ((float4*)xs)[i] = x4[i];
    __syncthreads();

    const int warp = tid >> 5;
    const int lane = tid & 31;
    const int r = blockIdx.x * 8 + warp;
    if (r >= E_TAIL) return;

    const float4* wrow =
        (const float4*)(w + ((size_t)b * E_TOT + D_OUT + r) * (size_t)D_IN);

    float acc = 0.f;
#pragma unroll
    for (int i = 0; i < 8; i++) {
        float4 wv = __ldcs(&wrow[i * 32 + lane]);
        float4 xv = ((const float4*)xs)[i * 32 + lane];
        acc += wv.x * xv.x + wv.y * xv.y + wv.z * xv.z + wv.w * xv.w;
    }
#pragma unroll
    for (int o = 16; o; o >>= 1)
        acc += __shfl_xor_sync(0xFFFFFFFFu, acc, o);

    if (lane == 0)
        g_out[b * E_TAIL + r] = acc;
}

// ---------------------------------------------------------------------------
// Kernel 2: per-batch softmax(k), softmax(q), diff = qphi - kphi, sigmoids.
// One block (256 threads) per batch; each thread owns 4 strided elements.
// ---------------------------------------------------------------------------
__global__ void __launch_bounds__(256) k2_softmax()
{
    const int b   = blockIdx.x;
    const int tid = threadIdx.x;
    __shared__ float red[256];

    const float* ob = g_out + b * E_TAIL;

    // ---- k softmax ----
    float kv[4];
#pragma unroll
    for (int j = 0; j < 4; j++) kv[j] = ob[tid + j * 256];
    float m = fmaxf(fmaxf(kv[0], kv[1]), fmaxf(kv[2], kv[3]));
    red[tid] = m; __syncthreads();
    for (int s = 128; s; s >>= 1) {
        if (tid < s) red[tid] = fmaxf(red[tid], red[tid + s]);
        __syncthreads();
    }
    m = red[0]; __syncthreads();

    float sum = 0.f;
#pragma unroll
    for (int j = 0; j < 4; j++) { kv[j] = __expf(kv[j] - m); sum += kv[j]; }
    red[tid] = sum; __syncthreads();
    for (int s = 128; s; s >>= 1) {
        if (tid < s) red[tid] += red[tid + s];
        __syncthreads();
    }
    float inv = 1.f / red[0]; __syncthreads();
#pragma unroll
    for (int j = 0; j < 4; j++) {
        kv[j] *= inv;
        g_kphi[b * D_IN + tid + j * 256] = kv[j];
    }

    // ---- q softmax, diff ----
    float qv[4];
#pragma unroll
    for (int j = 0; j < 4; j++) qv[j] = ob[D_IN + tid + j * 256];
    m = fmaxf(fmaxf(qv[0], qv[1]), fmaxf(qv[2], qv[3]));
    red[tid] = m; __syncthreads();
    for (int s = 128; s; s >>= 1) {
        if (tid < s) red[tid] = fmaxf(red[tid], red[tid + s]);
        __syncthreads();
    }
    m = red[0]; __syncthreads();

    sum = 0.f;
#pragma unroll
    for (int j = 0; j < 4; j++) { qv[j] = __expf(qv[j] - m); sum += qv[j]; }
    red[tid] = sum; __syncthreads();
    for (int s = 128; s; s >>= 1) {
        if (tid < s) red[tid] += red[tid + s];
        __syncthreads();
    }
    inv = 1.f / red[0];
#pragma unroll
    for (int j = 0; j < 4; j++)
        g_diff[b * D_IN + tid + j * 256] = qv[j] * inv - kv[j];

    // ---- sigmoids of the 4 bias scalars (rows E-4..E-1 -> scratch 2048..2051)
    if (tid < 4)
        g_sigb[b * 4 + tid] = 1.f / (1.f + __expf(-ob[2 * D_IN + tid]));
}

// ---------------------------------------------------------------------------
// Kernel 3 (fused): per row e of w:
//   dd = dot(w_row, diff)        (= v[e] - vbar[e])
//   dx = dot(w_row, x)           (y[e] for e < D_OUT)
//   s  = sigmoid(beta[e]) * dd
//   w_out_row = w_row + s * kphi
// Row held in registers between the dots and the write (single read of w).
// ---------------------------------------------------------------------------
__global__ void __launch_bounds__(256) k3_update(const float* __restrict__ x,
                                                 const float* __restrict__ w,
                                                 float* __restrict__ y,
                                                 float* __restrict__ wout)
{
    __shared__ float xs[D_IN];
    __shared__ float ds[D_IN];
    __shared__ float ks[D_IN];
    const int b   = blockIdx.y;
    const int tid = threadIdx.x;

    for (int i = tid; i < D_IN / 4; i += 256) {
        ((float4*)xs)[i] = ((const float4*)(x      + (size_t)b * D_IN))[i];
        ((float4*)ds)[i] = ((const float4*)(g_diff + (size_t)b * D_IN))[i];
        ((float4*)ks)[i] = ((const float4*)(g_kphi + (size_t)b * D_IN))[i];
    }
    __syncthreads();

    const int warp = tid >> 5;
    const int lane = tid & 31;
    const int e = blockIdx.x * 8 + warp;
    if (e >= E_TOT) return;

    const size_t off = ((size_t)b * E_TOT + e) * (size_t)D_IN;
    const float4* wrow = (const float4*)(w    + off);
    float4*       orow = (float4*)      (wout + off);

    float4 wr[8];
    float dd = 0.f, dx = 0.f;
#pragma unroll
    for (int i = 0; i < 8; i++) {
        wr[i] = __ldcs(&wrow[i * 32 + lane]);
        float4 dv = ((const float4*)ds)[i * 32 + lane];
        float4 xv = ((const float4*)xs)[i * 32 + lane];
        dd += wr[i].x * dv.x + wr[i].y * dv.y + wr[i].z * dv.z + wr[i].w * dv.w;
        dx += wr[i].x * xv.x + wr[i].y * xv.y + wr[i].z * xv.z + wr[i].w * xv.w;
    }
#pragma unroll
    for (int o = 16; o; o >>= 1) {
        dd += __shfl_xor_sync(0xFFFFFFFFu, dd, o);
        dx += __shfl_xor_sync(0xFFFFFFFFu, dx, o);
    }

    // beta region: [0,1024)->b1, [1024,2048)->b2, [2048,3072)->b3, [3072,3076)->b4
    const int region = (e < 1024) ? 0 : (e < 2048) ? 1 : (e < 3072) ? 2 : 3;
    const float s = g_sigb[b * 4 + region] * dd;

#pragma unroll
    for (int i = 0; i < 8; i++) {
        float4 kv = ((const float4*)ks)[i * 32 + lane];
        float4 o;
        o.x = wr[i].x + s * kv.x;
        o.y = wr[i].y + s * kv.y;
        o.z = wr[i].z + s * kv.z;
        o.w = wr[i].w + s * kv.w;
        __stcs(&orow[i * 32 + lane], o);
    }

    if (e < D_OUT && lane == 0)
        y[(size_t)b * D_OUT + e] = dx;
}

// ---------------------------------------------------------------------------
extern "C" void kernel_launch(void* const* d_in, const int* in_sizes, int n_in,
                              void* d_out, int out_size)
{
    const float* x = (const float*)d_in[0];   // (32, 1024)
    const float* w = (const float*)d_in[1];   // (32, 3076, 1024)
    float* y    = (float*)d_out;              // (32, 1024)
    float* wout = y + (size_t)BATCH * D_OUT;  // (32, 3076, 1024)

    dim3 g1((E_TAIL + 7) / 8, BATCH);
    k1_gemv<<<g1, 256>>>(x, w);

    k2_softmax<<<BATCH, 256>>>();

    dim3 g3((E_TOT + 7) / 8, BATCH);
    k3_update<<<g3, 256>>>(x, w, y, wout);
}

// round 4
// speedup vs baseline: 1.0235x; 1.0235x over previous
#include <cuda_runtime.h>

#define D_IN   1024
#define D_OUT  1024
#define BATCH  32
#define E_TOT  3076              // D_OUT + 2*D_IN + 4
#define E_TAIL 2052              // E_TOT - D_OUT (rows needed in pass 1)

// Scratch (device globals; no allocation allowed)
__device__ float g_out [BATCH * E_TAIL];   // w·x for rows [D_OUT, E)
__device__ float g_kphi[BATCH * D_IN];     // softmax(k)
__device__ float g_diff[BATCH * D_IN];     // softmax(q) - softmax(k)
__device__ float g_sigb[BATCH * 4];        // sigmoid(b1..b4)

// ---------------------------------------------------------------------------
// Kernel 1: out[b, e] = dot(w[b, D_OUT+e, :], x[b, :]) for e in [0, E_TAIL)
// warp-per-row. DEFAULT-cached loads: the last ~126 MB of this stream stays
// resident in L2 for k3 to consume (k3 traverses in reverse order).
// ---------------------------------------------------------------------------
__global__ void __launch_bounds__(256) k1_gemv(const float* __restrict__ x,
                                               const float* __restrict__ w)
{
    __shared__ float xs[D_IN];
    const int b   = blockIdx.y;
    const int tid = threadIdx.x;

    const float4* x4 = (const float4*)(x + (size_t)b * D_IN);
    for (int i = tid; i < D_IN / 4; i += 256)
        ((float4*)xs)[i] = x4[i];
    __syncthreads();

    const int warp = tid >> 5;
    const int lane = tid & 31;
    const int r = blockIdx.x * 8 + warp;
    if (r >= E_TAIL) return;

    const float4* wrow =
        (const float4*)(w + ((size_t)b * E_TOT + D_OUT + r) * (size_t)D_IN);

    float acc = 0.f;
#pragma unroll
    for (int i = 0; i < 8; i++) {
        float4 wv = __ldg(&wrow[i * 32 + lane]);        // cache in L2
        float4 xv = ((const float4*)xs)[i * 32 + lane];
        acc += wv.x * xv.x + wv.y * xv.y + wv.z * xv.z + wv.w * xv.w;
    }
#pragma unroll
    for (int o = 16; o; o >>= 1)
        acc += __shfl_xor_sync(0xFFFFFFFFu, acc, o);

    if (lane == 0)
        g_out[b * E_TAIL + r] = acc;
}

// ---------------------------------------------------------------------------
// Kernel 2: per-batch softmax(k), softmax(q), diff = qphi - kphi, sigmoids.
// ---------------------------------------------------------------------------
__global__ void __launch_bounds__(256) k2_softmax()
{
    const int b   = blockIdx.x;
    const int tid = threadIdx.x;
    __shared__ float red[256];

    const float* ob = g_out + b * E_TAIL;

    // ---- k softmax ----
    float kv[4];
#pragma unroll
    for (int j = 0; j < 4; j++) kv[j] = ob[tid + j * 256];
    float m = fmaxf(fmaxf(kv[0], kv[1]), fmaxf(kv[2], kv[3]));
    red[tid] = m; __syncthreads();
    for (int s = 128; s; s >>= 1) {
        if (tid < s) red[tid] = fmaxf(red[tid], red[tid + s]);
        __syncthreads();
    }
    m = red[0]; __syncthreads();

    float sum = 0.f;
#pragma unroll
    for (int j = 0; j < 4; j++) { kv[j] = __expf(kv[j] - m); sum += kv[j]; }
    red[tid] = sum; __syncthreads();
    for (int s = 128; s; s >>= 1) {
        if (tid < s) red[tid] += red[tid + s];
        __syncthreads();
    }
    float inv = 1.f / red[0]; __syncthreads();
#pragma unroll
    for (int j = 0; j < 4; j++) {
        kv[j] *= inv;
        g_kphi[b * D_IN + tid + j * 256] = kv[j];
    }

    // ---- q softmax, diff ----
    float qv[4];
#pragma unroll
    for (int j = 0; j < 4; j++) qv[j] = ob[D_IN + tid + j * 256];
    m = fmaxf(fmaxf(qv[0], qv[1]), fmaxf(qv[2], qv[3]));
    red[tid] = m; __syncthreads();
    for (int s = 128; s; s >>= 1) {
        if (tid < s) red[tid] = fmaxf(red[tid], red[tid + s]);
        __syncthreads();
    }
    m = red[0]; __syncthreads();

    sum = 0.f;
#pragma unroll
    for (int j = 0; j < 4; j++) { qv[j] = __expf(qv[j] - m); sum += qv[j]; }
    red[tid] = sum; __syncthreads();
    for (int s = 128; s; s >>= 1) {
        if (tid < s) red[tid] += red[tid + s];
        __syncthreads();
    }
    inv = 1.f / red[0];
#pragma unroll
    for (int j = 0; j < 4; j++)
        g_diff[b * D_IN + tid + j * 256] = qv[j] * inv - kv[j];

    if (tid < 4)
        g_sigb[b * 4 + tid] = 1.f / (1.f + __expf(-ob[2 * D_IN + tid]));
}

// ---------------------------------------------------------------------------
// Kernel 3 (fused): per row e of w:
//   dd = dot(w_row, diff); dx = dot(w_row, x)
//   w_out_row = w_row + sigmoid(beta[e]) * dd * kphi
// Traversal REVERSED vs k1 (batch descending, rows descending from E_TOT-1)
// so its first reads hit the L2 remnant k1 left behind. __ldcs/__stcs keep
// the cold streams from evicting that remnant.
// ---------------------------------------------------------------------------
__global__ void __launch_bounds__(256) k3_update(const float* __restrict__ x,
                                                 const float* __restrict__ w,
                                                 float* __restrict__ y,
                                                 float* __restrict__ wout)
{
    __shared__ float xs[D_IN];
    __shared__ float ds[D_IN];
    __shared__ float ks[D_IN];
    const int b   = BATCH - 1 - blockIdx.y;          // reverse batch order
    const int tid = threadIdx.x;

    for (int i = tid; i < D_IN / 4; i += 256) {
        ((float4*)xs)[i] = ((const float4*)(x      + (size_t)b * D_IN))[i];
        ((float4*)ds)[i] = ((const float4*)(g_diff + (size_t)b * D_IN))[i];
        ((float4*)ks)[i] = ((const float4*)(g_kphi + (size_t)b * D_IN))[i];
    }
    __syncthreads();

    const int warp = tid >> 5;
    const int lane = tid & 31;
    const int idx = blockIdx.x * 8 + warp;
    if (idx >= E_TOT) return;
    const int e = E_TOT - 1 - idx;                   // reverse row order

    const size_t off = ((size_t)b * E_TOT + e) * (size_t)D_IN;
    const float4* wrow = (const float4*)(w    + off);
    float4*       orow = (float4*)      (wout + off);

    float4 wr[8];
    float dd = 0.f, dx = 0.f;
#pragma unroll
    for (int i = 0; i < 8; i++) {
        wr[i] = __ldcs(&wrow[i * 32 + lane]);        // hit L2 remnant, evict-first
        float4 dv = ((const float4*)ds)[i * 32 + lane];
        float4 xv = ((const float4*)xs)[i * 32 + lane];
        dd += wr[i].x * dv.x + wr[i].y * dv.y + wr[i].z * dv.z + wr[i].w * dv.w;
        dx += wr[i].x * xv.x + wr[i].y * xv.y + wr[i].z * xv.z + wr[i].w * xv.w;
    }
#pragma unroll
    for (int o = 16; o; o >>= 1) {
        dd += __shfl_xor_sync(0xFFFFFFFFu, dd, o);
        dx += __shfl_xor_sync(0xFFFFFFFFu, dx, o);
    }

    // beta region: [0,1024)->b1, [1024,2048)->b2, [2048,3072)->b3, [3072,3076)->b4
    const int region = (e < 1024) ? 0 : (e < 2048) ? 1 : (e < 3072) ? 2 : 3;
    const float s = g_sigb[b * 4 + region] * dd;

#pragma unroll
    for (int i = 0; i < 8; i++) {
        float4 kv = ((const float4*)ks)[i * 32 + lane];
        float4 o;
        o.x = wr[i].x + s * kv.x;
        o.y = wr[i].y + s * kv.y;
        o.z = wr[i].z + s * kv.z;
        o.w = wr[i].w + s * kv.w;
        __stcs(&orow[i * 32 + lane], o);
    }

    if (e < D_OUT && lane == 0)
        y[(size_t)b * D_OUT + e] = dx;
}

// ---------------------------------------------------------------------------
extern "C" void kernel_launch(void* const* d_in, const int* in_sizes, int n_in,
                              void* d_out, int out_size)
{
    const float* x = (const float*)d_in[0];   // (32, 1024)
    const float* w = (const float*)d_in[1];   // (32, 3076, 1024)
    float* y    = (float*)d_out;              // (32, 1024)
    float* wout = y + (size_t)BATCH * D_OUT;  // (32, 3076, 1024)

    dim3 g1((E_TAIL + 7) / 8, BATCH);
    k1_gemv<<<g1, 256>>>(x, w);

    k2_softmax<<<BATCH, 256>>>();

    dim3 g3((E_TOT + 7) / 8, BATCH);
    k3_update<<<g3, 256>>>(x, w, y, wout);
}

// round 6
// speedup vs baseline: 1.0296x; 1.0060x over previous
#include <cuda_runtime.h>

#define D_IN   1024
#define D_OUT  1024
#define BATCH  32
#define E_TOT  3076              // D_OUT + 2*D_IN + 4
#define E_TAIL 2052              // E_TOT - D_OUT (rows needed in pass 1)
#define B_KEEP 19                // batches >= B_KEEP cached normal in k1 (~110 MB)

// Scratch (device globals; no allocation allowed)
__device__ float g_out [BATCH * E_TAIL];   // w·x for rows [D_OUT, E)
__device__ float g_kphi[BATCH * D_IN];     // softmax(k)
__device__ float g_diff[BATCH * D_IN];     // softmax(q) - softmax(k)
__device__ float g_sigb[BATCH * 4];        // sigmoid(b1..b4)

// ---------------------------------------------------------------------------
// Kernel 1: out[b, e] = dot(w[b, D_OUT+e, :], x[b, :]) for e in [0, E_TAIL)
// warp-per-row. Cache-policy split: batches that k3 (reverse order) can reach
// before eviction are inserted evict-normal; the rest evict-first so they
// never displace the reusable remnant.
// ---------------------------------------------------------------------------
__global__ void __launch_bounds__(256) k1_gemv(const float* __restrict__ x,
                                               const float* __restrict__ w)
{
    __shared__ float xs[D_IN];
    const int b   = blockIdx.y;
    const int tid = threadIdx.x;

    const float4* x4 = (const float4*)(x + (size_t)b * D_IN);
    for (int i = tid; i < D_IN / 4; i += 256)
        ((float4*)xs)[i] = x4[i];
    __syncthreads();

    const int warp = tid >> 5;
    const int lane = tid & 31;
    const int r = blockIdx.x * 8 + warp;
    if (r >= E_TAIL) return;

    const float4* wrow =
        (const float4*)(w + ((size_t)b * E_TOT + D_OUT + r) * (size_t)D_IN);

    float acc = 0.f;
    if (b >= B_KEEP) {
#pragma unroll
        for (int i = 0; i < 8; i++) {
            float4 wv = __ldg(&wrow[i * 32 + lane]);    // keep in L2 for k3
            float4 xv = ((const float4*)xs)[i * 32 + lane];
            acc += wv.x * xv.x + wv.y * xv.y + wv.z * xv.z + wv.w * xv.w;
        }
    } else {
#pragma unroll
        for (int i = 0; i < 8; i++) {
            float4 wv = __ldcs(&wrow[i * 32 + lane]);   // unreachable by k3: evict-first
            float4 xv = ((const float4*)xs)[i * 32 + lane];
            acc += wv.x * xv.x + wv.y * xv.y + wv.z * xv.z + wv.w * xv.w;
        }
    }
#pragma unroll
    for (int o = 16; o; o >>= 1)
        acc += __shfl_xor_sync(0xFFFFFFFFu, acc, o);

    if (lane == 0)
        g_out[b * E_TAIL + r] = acc;
}

// ---------------------------------------------------------------------------
// Kernel 2: per-batch softmax(k), softmax(q), diff = qphi - kphi, sigmoids.
// ---------------------------------------------------------------------------
__global__ void __launch_bounds__(256) k2_softmax()
{
    const int b   = blockIdx.x;
    const int tid = threadIdx.x;
    __shared__ float red[256];

    const float* ob = g_out + b * E_TAIL;

    // ---- k softmax ----
    float kv[4];
#pragma unroll
    for (int j = 0; j < 4; j++) kv[j] = ob[tid + j * 256];
    float m = fmaxf(fmaxf(kv[0], kv[1]), fmaxf(kv[2], kv[3]));
    red[tid] = m; __syncthreads();
    for (int s = 128; s; s >>= 1) {
        if (tid < s) red[tid] = fmaxf(red[tid], red[tid + s]);
        __syncthreads();
    }
    m = red[0]; __syncthreads();

    float sum = 0.f;
#pragma unroll
    for (int j = 0; j < 4; j++) { kv[j] = __expf(kv[j] - m); sum += kv[j]; }
    red[tid] = sum; __syncthreads();
    for (int s = 128; s; s >>= 1) {
        if (tid < s) red[tid] += red[tid + s];
        __syncthreads();
    }
    float inv = 1.f / red[0]; __syncthreads();
#pragma unroll
    for (int j = 0; j < 4; j++) {
        kv[j] *= inv;
        g_kphi[b * D_IN + tid + j * 256] = kv[j];
    }

    // ---- q softmax, diff ----
    float qv[4];
#pragma unroll
    for (int j = 0; j < 4; j++) qv[j] = ob[D_IN + tid + j * 256];
    m = fmaxf(fmaxf(qv[0], qv[1]), fmaxf(qv[2], qv[3]));
    red[tid] = m; __syncthreads();
    for (int s = 128; s; s >>= 1) {
        if (tid < s) red[tid] = fmaxf(red[tid], red[tid + s]);
        __syncthreads();
    }
    m = red[0]; __syncthreads();

    sum = 0.f;
#pragma unroll
    for (int j = 0; j < 4; j++) { qv[j] = __expf(qv[j] - m); sum += qv[j]; }
    red[tid] = sum; __syncthreads();
    for (int s = 128; s; s >>= 1) {
        if (tid < s) red[tid] += red[tid + s];
        __syncthreads();
    }
    inv = 1.f / red[0];
#pragma unroll
    for (int j = 0; j < 4; j++)
        g_diff[b * D_IN + tid + j * 256] = qv[j] * inv - kv[j];

    if (tid < 4)
        g_sigb[b * 4 + tid] = 1.f / (1.f + __expf(-ob[2 * D_IN + tid]));
}

// ---------------------------------------------------------------------------
// Kernel 3 (fused): per row e of w:
//   dd = dot(w_row, diff); dx = dot(w_row, x)
//   w_out_row = w_row + sigmoid(beta[e]) * dd * kphi
// Reverse traversal (batch desc, rows desc) to consume k1's L2 remnant.
// Reads __ldcs (hit-or-stream, no pollution); stores __stwt (write-through:
// w_out is never re-read, so don't let it allocate L2 lines at all).
// ---------------------------------------------------------------------------
__global__ void __launch_bounds__(256) k3_update(const float* __restrict__ x,
                                                 const float* __restrict__ w,
                                                 float* __restrict__ y,
                                                 float* __restrict__ wout)
{
    __shared__ float xs[D_IN];
    __shared__ float ds[D_IN];
    __shared__ float ks[D_IN];
    const int b   = BATCH - 1 - blockIdx.y;          // reverse batch order
    const int tid = threadIdx.x;

    for (int i = tid; i < D_IN / 4; i += 256) {
        ((float4*)xs)[i] = ((const float4*)(x      + (size_t)b * D_IN))[i];
        ((float4*)ds)[i] = ((const float4*)(g_diff + (size_t)b * D_IN))[i];
        ((float4*)ks)[i] = ((const float4*)(g_kphi + (size_t)b * D_IN))[i];
    }
    __syncthreads();

    const int warp = tid >> 5;
    const int lane = tid & 31;
    const int idx = blockIdx.x * 8 + warp;
    if (idx >= E_TOT) return;
    const int e = E_TOT - 1 - idx;                   // reverse row order

    const size_t off = ((size_t)b * E_TOT + e) * (size_t)D_IN;
    const float4* wrow = (const float4*)(w    + off);
    float4*       orow = (float4*)      (wout + off);

    float4 wr[8];
    float dd = 0.f, dx = 0.f;
#pragma unroll
    for (int i = 0; i < 8; i++) {
        wr[i] = __ldcs(&wrow[i * 32 + lane]);        // hit L2 remnant, else stream
        float4 dv = ((const float4*)ds)[i * 32 + lane];
        float4 xv = ((const float4*)xs)[i * 32 + lane];
        dd += wr[i].x * dv.x + wr[i].y * dv.y + wr[i].z * dv.z + wr[i].w * dv.w;
        dx += wr[i].x * xv.x + wr[i].y * xv.y + wr[i].z * xv.z + wr[i].w * xv.w;
    }
#pragma unroll
    for (int o = 16; o; o >>= 1) {
        dd += __shfl_xor_sync(0xFFFFFFFFu, dd, o);
        dx += __shfl_xor_sync(0xFFFFFFFFu, dx, o);
    }

    // beta region: [0,1024)->b1, [1024,2048)->b2, [2048,3072)->b3, [3072,3076)->b4
    const int region = (e < 1024) ? 0 : (e < 2048) ? 1 : (e < 3072) ? 2 : 3;
    const float s = g_sigb[b * 4 + region] * dd;

#pragma unroll
    for (int i = 0; i < 8; i++) {
        float4 kv = ((const float4*)ks)[i * 32 + lane];
        float4 o;
        o.x = wr[i].x + s * kv.x;
        o.y = wr[i].y + s * kv.y;
        o.z = wr[i].z + s * kv.z;
        o.w = wr[i].w + s * kv.w;
        __stwt(&orow[i * 32 + lane], o);             // write-through: no L2 allocation
    }

    if (e < D_OUT && lane == 0)
        y[(size_t)b * D_OUT + e] = dx;
}

// ---------------------------------------------------------------------------
extern "C" void kernel_launch(void* const* d_in, const int* in_sizes, int n_in,
                              void* d_out, int out_size)
{
    const float* x = (const float*)d_in[0];   // (32, 1024)
    const float* w = (const float*)d_in[1];   // (32, 3076, 1024)
    float* y    = (float*)d_out;              // (32, 1024)
    float* wout = y + (size_t)BATCH * D_OUT;  // (32, 3076, 1024)

    dim3 g1((E_TAIL + 7) / 8, BATCH);
    k1_gemv<<<g1, 256>>>(x, w);

    k2_softmax<<<BATCH, 256>>>();

    dim3 g3((E_TOT + 7) / 8, BATCH);
    k3_update<<<g3, 256>>>(x, w, y, wout);
}